// round 4
// baseline (speedup 1.0000x reference)
#include <cuda_runtime.h>
#include <cuda_fp16.h>

namespace {

constexpr int H = 128, W = 128, D = 128;
constexpr int N = H * W * D;          // 2^21
constexpr int B = 2;

// brick / tile geometry
constexpr int BX = 16, BY = 16, BZ = 32;        // voxels per block
constexpr int HALO = 10;
constexpr int TX = BX + 2 * HALO + 1;           // 37
constexpr int TY = BY + 2 * HALO + 1;           // 37
constexpr int TZE = BZ + 2 * HALO + 1;          // 53 usable z entries
constexpr int TZ = TZE + 1;                     // 54 (pad to even for u32 staging)
constexpr int TILE_U32 = TX * TY * (TZ / 2);    // 36963
constexpr int SMEM_BYTES = TX * TY * TZ * 2;    // 147852

// fp16 copy of the image (serves staging reads + rare fallback gathers)
__device__ __align__(16) __half g_img16[(size_t)B * N];

// ---------------- prepass: fp32 image -> fp16 copy ----------------
__global__ __launch_bounds__(256) void pack16_kernel(const float* __restrict__ img) {
    int t = blockIdx.x * blockDim.x + threadIdx.x;
    int base = t * 8;
    float4 a = *reinterpret_cast<const float4*>(img + base);
    float4 c = *reinterpret_cast<const float4*>(img + base + 4);
    __half2 h[4];
    h[0] = __floats2half2_rn(a.x, a.y);
    h[1] = __floats2half2_rn(a.z, a.w);
    h[2] = __floats2half2_rn(c.x, c.y);
    h[3] = __floats2half2_rn(c.z, c.w);
    *reinterpret_cast<uint4*>(g_img16 + base) = *reinterpret_cast<uint4*>(h);
}

// rare fallback: fully masked trilinear gather from global fp16 image
__device__ __noinline__ float sample_masked(const __half* __restrict__ img,
                                            float tx, float ty, float tz,
                                            int x0, int y0, int z0) {
    int x1 = x0 + 1, y1 = y0 + 1, z1 = z0 + 1;
    float wx0 = ((unsigned)x0 < (unsigned)H) ? (1.0f - tx) : 0.0f;
    float wx1 = ((unsigned)x1 < (unsigned)H) ? tx          : 0.0f;
    float wy0 = ((unsigned)y0 < (unsigned)W) ? (1.0f - ty) : 0.0f;
    float wy1 = ((unsigned)y1 < (unsigned)W) ? ty          : 0.0f;
    float wz0 = ((unsigned)z0 < (unsigned)D) ? (1.0f - tz) : 0.0f;
    float wz1 = ((unsigned)z1 < (unsigned)D) ? tz          : 0.0f;
    int cx0 = min(max(x0, 0), H - 1), cx1 = min(max(x1, 0), H - 1);
    int cy0 = min(max(y0, 0), W - 1), cy1 = min(max(y1, 0), W - 1);
    int cz0 = min(max(z0, 0), D - 1), cz1 = min(max(z1, 0), D - 1);
    int bx0 = cx0 * (W * D), bx1 = cx1 * (W * D);
    int by0 = cy0 * D,       by1 = cy1 * D;
    float v000 = __half2float(__ldg(img + bx0 + by0 + cz0));
    float v001 = __half2float(__ldg(img + bx0 + by0 + cz1));
    float v010 = __half2float(__ldg(img + bx0 + by1 + cz0));
    float v011 = __half2float(__ldg(img + bx0 + by1 + cz1));
    float v100 = __half2float(__ldg(img + bx1 + by0 + cz0));
    float v101 = __half2float(__ldg(img + bx1 + by0 + cz1));
    float v110 = __half2float(__ldg(img + bx1 + by1 + cz0));
    float v111 = __half2float(__ldg(img + bx1 + by1 + cz1));
    float c00 = fmaf(wz0, v000, wz1 * v001);
    float c01 = fmaf(wz0, v010, wz1 * v011);
    float c10 = fmaf(wz0, v100, wz1 * v101);
    float c11 = fmaf(wz0, v110, wz1 * v111);
    float d0 = fmaf(wy0, c00, wy1 * c01);
    float d1 = fmaf(wy0, c10, wy1 * c11);
    return fmaf(wx0, d0, wx1 * d1);
}

// ---------------- main kernel: one 16x16x32 brick per block ----------------
__global__ __launch_bounds__(1024, 1) void warp_kernel(const float* __restrict__ ddf,
                                                       float* __restrict__ out) {
    extern __shared__ __half tile[];   // [TX][TY][TZ]

    int bid = blockIdx.x;
    int bz = bid & 3;
    int by = (bid >> 2) & 7;
    int bx = (bid >> 5) & 7;
    int b  = bid >> 8;

    int X0 = bx * BX, Y0 = by * BY, Z0 = bz * BZ;
    int gx0 = X0 - HALO, gy0 = Y0 - HALO, gz0 = Z0 - HALO;   // gz0 even

    const __half* img = g_img16 + (size_t)b * N;
    int tid = threadIdx.x;

    // ---- stage tile (u32 = 2 halves along z), zeros outside the volume ----
    uint* tile32 = reinterpret_cast<uint*>(tile);
    for (int s = tid; s < TILE_U32; s += 1024) {
        int k2 = s % (TZ / 2);
        int rem = s / (TZ / 2);
        int j = rem % TY;
        int i = rem / TY;
        int gx = gx0 + i, gy = gy0 + j, gz = gz0 + 2 * k2;
        uint val = 0u;
        if ((unsigned)gx < (unsigned)H && (unsigned)gy < (unsigned)W) {
            int rb = (gx * W + gy) * D;
            if ((unsigned)gz < (unsigned)(D - 1)) {          // gz in [0,126]: both halves in
                val = *reinterpret_cast<const uint*>(img + rb + gz);  // aligned: rb, gz even
            } else {
                __half lo = ((unsigned)gz < (unsigned)D) ? img[rb + gz] : __half(0.0f);
                __half hi = ((unsigned)(gz + 1) < (unsigned)D) ? img[rb + gz + 1] : __half(0.0f);
                __half2 h2 = __halves2half2(lo, hi);
                val = *reinterpret_cast<uint*>(&h2);
            }
        }
        tile32[s] = val;
    }
    __syncthreads();

    // ---- compute: 8 iterations, one (x,y) row of 32 z-voxels per warp ----
    int warp = tid >> 5, lane = tid & 31;
    const float* dbase0 = ddf + (size_t)b * 3 * N;
    float* outb = out + (size_t)b * N;

    #pragma unroll
    for (int it = 0; it < 8; it++) {
        int row = it * 32 + warp;        // 0..255
        int xl = row >> 4, yl = row & 15;
        int x = X0 + xl, y = Y0 + yl, z = Z0 + lane;
        int r = (x * W + y) * D + z;

        float fx = (float)x + __ldg(dbase0 + r);
        float fy = (float)y + __ldg(dbase0 + N + r);
        float fz = (float)z + __ldg(dbase0 + 2 * N + r);

        float x0f = floorf(fx), y0f = floorf(fy), z0f = floorf(fz);
        float tx = fx - x0f, ty = fy - y0f, tz = fz - z0f;
        int x0 = (int)x0f, y0 = (int)y0f, z0 = (int)z0f;

        int x0l = x0 - gx0, y0l = y0 - gy0, z0l = z0 - gz0;
        bool bad = ((unsigned)x0l > (unsigned)(TX - 2)) |
                   ((unsigned)y0l > (unsigned)(TY - 2)) |
                   ((unsigned)z0l > (unsigned)(TZE - 2));

        float res;
        if (!bad) {
            // zeros-padding already baked into the staged tile: no masking needed
            int base = (x0l * TY + y0l) * TZ + z0l;
            float v000 = __half2float(tile[base]);
            float v001 = __half2float(tile[base + 1]);
            float v010 = __half2float(tile[base + TZ]);
            float v011 = __half2float(tile[base + TZ + 1]);
            float v100 = __half2float(tile[base + TY * TZ]);
            float v101 = __half2float(tile[base + TY * TZ + 1]);
            float v110 = __half2float(tile[base + TY * TZ + TZ]);
            float v111 = __half2float(tile[base + TY * TZ + TZ + 1]);
            float c00 = fmaf(1.0f - tz, v000, tz * v001);
            float c01 = fmaf(1.0f - tz, v010, tz * v011);
            float c10 = fmaf(1.0f - tz, v100, tz * v101);
            float c11 = fmaf(1.0f - tz, v110, tz * v111);
            float d0 = fmaf(1.0f - ty, c00, ty * c01);
            float d1 = fmaf(1.0f - ty, c10, ty * c11);
            res = fmaf(1.0f - tx, d0, tx * d1);
        } else {
            res = sample_masked(img, tx, ty, tz, x0, y0, z0);
        }
        outb[r] = res;
    }
}

} // namespace

extern "C" void kernel_launch(void* const* d_in, const int* in_sizes, int n_in,
                              void* d_out, int out_size) {
    const float* image = (const float*)d_in[0];  // (B, 1, H, W, D) fp32
    const float* ddf   = (const float*)d_in[1];  // (B, 3, H, W, D) fp32
    float* out         = (float*)d_out;          // (B, 1, H, W, D) fp32

    static bool attr_set = false;
    if (!attr_set) {
        cudaFuncSetAttribute(warp_kernel, cudaFuncAttributeMaxDynamicSharedMemorySize,
                             SMEM_BYTES);
        attr_set = true;
    }

    int pack_threads = (B * N) / 8;              // 524,288
    pack16_kernel<<<pack_threads / 256, 256>>>(image);

    int bricks = B * (H / BX) * (W / BY) * (D / BZ);   // 512
    warp_kernel<<<bricks, 1024, SMEM_BYTES>>>(ddf, out);
}

// round 5
// speedup vs baseline: 1.5145x; 1.5145x over previous
#include <cuda_runtime.h>
#include <cuda_fp16.h>

namespace {

constexpr int H = 128, W = 128, D = 128;
constexpr int N = H * W * D;          // 2^21
constexpr int B = 2;

// brick / tile geometry
constexpr int BX = 16, BY = 16, BZ = 32;        // voxels per block
constexpr int HALO = 10;
constexpr int TX = BX + 2 * HALO + 1;           // 37
constexpr int TY = BY + 2 * HALO + 1;           // 37
constexpr int TZE = BZ + 2 * HALO + 1;          // 53 usable z entries
constexpr int TZ = 64;                          // padded: one warp = one row (32 u32)
constexpr int NROWS = TX * TY;                  // 1369
constexpr int SMEM_BYTES = NROWS * TZ * 2;      // 175,232

// fp16 copy of the image (serves staging reads + rare fallback gathers)
__device__ __align__(16) __half g_img16[(size_t)B * N];

// ---------------- prepass: fp32 image -> fp16 copy ----------------
__global__ __launch_bounds__(256) void pack16_kernel(const float* __restrict__ img) {
    int t = blockIdx.x * blockDim.x + threadIdx.x;
    int base = t * 8;
    float4 a = *reinterpret_cast<const float4*>(img + base);
    float4 c = *reinterpret_cast<const float4*>(img + base + 4);
    __half2 h[4];
    h[0] = __floats2half2_rn(a.x, a.y);
    h[1] = __floats2half2_rn(a.z, a.w);
    h[2] = __floats2half2_rn(c.x, c.y);
    h[3] = __floats2half2_rn(c.z, c.w);
    *reinterpret_cast<uint4*>(g_img16 + base) = *reinterpret_cast<uint4*>(h);
}

// rare fallback: fully masked trilinear gather from global fp16 image
__device__ __noinline__ float sample_masked(const __half* __restrict__ img,
                                            float tx, float ty, float tz,
                                            int x0, int y0, int z0) {
    int x1 = x0 + 1, y1 = y0 + 1, z1 = z0 + 1;
    float wx0 = ((unsigned)x0 < (unsigned)H) ? (1.0f - tx) : 0.0f;
    float wx1 = ((unsigned)x1 < (unsigned)H) ? tx          : 0.0f;
    float wy0 = ((unsigned)y0 < (unsigned)W) ? (1.0f - ty) : 0.0f;
    float wy1 = ((unsigned)y1 < (unsigned)W) ? ty          : 0.0f;
    float wz0 = ((unsigned)z0 < (unsigned)D) ? (1.0f - tz) : 0.0f;
    float wz1 = ((unsigned)z1 < (unsigned)D) ? tz          : 0.0f;
    int cx0 = min(max(x0, 0), H - 1), cx1 = min(max(x1, 0), H - 1);
    int cy0 = min(max(y0, 0), W - 1), cy1 = min(max(y1, 0), W - 1);
    int cz0 = min(max(z0, 0), D - 1), cz1 = min(max(z1, 0), D - 1);
    int bx0 = cx0 * (W * D), bx1 = cx1 * (W * D);
    int by0 = cy0 * D,       by1 = cy1 * D;
    float v000 = __half2float(__ldg(img + bx0 + by0 + cz0));
    float v001 = __half2float(__ldg(img + bx0 + by0 + cz1));
    float v010 = __half2float(__ldg(img + bx0 + by1 + cz0));
    float v011 = __half2float(__ldg(img + bx0 + by1 + cz1));
    float v100 = __half2float(__ldg(img + bx1 + by0 + cz0));
    float v101 = __half2float(__ldg(img + bx1 + by0 + cz1));
    float v110 = __half2float(__ldg(img + bx1 + by1 + cz0));
    float v111 = __half2float(__ldg(img + bx1 + by1 + cz1));
    float c00 = fmaf(wz0, v000, wz1 * v001);
    float c01 = fmaf(wz0, v010, wz1 * v011);
    float c10 = fmaf(wz0, v100, wz1 * v101);
    float c11 = fmaf(wz0, v110, wz1 * v111);
    float d0 = fmaf(wy0, c00, wy1 * c01);
    float d1 = fmaf(wy0, c10, wy1 * c11);
    return fmaf(wx0, d0, wx1 * d1);
}

// ---------------- main kernel: one 16x16x32 brick per block ----------------
__global__ __launch_bounds__(1024, 1) void warp_kernel(const float* __restrict__ ddf,
                                                       float* __restrict__ out) {
    extern __shared__ __half tile[];   // [TX][TY][TZ=64]

    int bid = blockIdx.x;
    int bz = bid & 3;
    int by = (bid >> 2) & 7;
    int bx = (bid >> 5) & 7;
    int b  = bid >> 8;

    int X0 = bx * BX, Y0 = by * BY, Z0 = bz * BZ;
    int gx0 = X0 - HALO, gy0 = Y0 - HALO, gz0 = Z0 - HALO;   // gz0 even

    const __half* img = g_img16 + (size_t)b * N;
    int tid = threadIdx.x;
    int warp = tid >> 5, lane = tid & 31;

    // ---- stage: one warp per (x,y) row, one lane per u32 (2 halves) ----
    // Fully coalesced 128B global reads + coalesced STS; zeros outside volume.
    uint* tile32 = reinterpret_cast<uint*>(tile);
    int gz = gz0 + 2 * lane;                       // even; lane-consecutive
    bool zin = (unsigned)gz < (unsigned)(D - 1) || gz == D - 2; // gz in [0,126]
    zin = ((unsigned)gz <= (unsigned)(D - 2));
    for (int row = warp; row < NROWS; row += 32) {
        unsigned i = (unsigned)row / (unsigned)TY;     // uniform per warp
        unsigned j = (unsigned)row - i * TY;
        int gx = gx0 + (int)i, gy = gy0 + (int)j;
        uint val = 0u;
        if ((unsigned)gx < (unsigned)H && (unsigned)gy < (unsigned)W && zin) {
            int rb = (gx << 7 | gy) << 7;              // (gx*W + gy)*D
            val = *reinterpret_cast<const uint*>(img + rb + gz);
        }
        tile32[(row << 5) + lane] = val;
    }
    __syncthreads();

    // ---- compute: 8 iterations, one (x,y) column of 32 z-voxels per warp ----
    const float* dbase0 = ddf + (size_t)b * 3 * N;
    float* outb = out + (size_t)b * N;

    #pragma unroll
    for (int it = 0; it < 8; it++) {
        int row = it * 32 + warp;        // 0..255
        int xl = row >> 4, yl = row & 15;
        int x = X0 + xl, y = Y0 + yl, z = Z0 + lane;
        int r = ((x << 7 | y) << 7) | z;

        float fx = (float)x + __ldg(dbase0 + r);
        float fy = (float)y + __ldg(dbase0 + N + r);
        float fz = (float)z + __ldg(dbase0 + 2 * N + r);

        float x0f = floorf(fx), y0f = floorf(fy), z0f = floorf(fz);
        float tx = fx - x0f, ty = fy - y0f, tz = fz - z0f;
        int x0 = (int)x0f, y0 = (int)y0f, z0 = (int)z0f;

        int x0l = x0 - gx0, y0l = y0 - gy0, z0l = z0 - gz0;
        bool bad = ((unsigned)x0l > (unsigned)(TX - 2)) |
                   ((unsigned)y0l > (unsigned)(TY - 2)) |
                   ((unsigned)z0l > (unsigned)(TZE - 2));

        float res;
        if (!bad) {
            // zeros-padding baked into the tile: unmasked 8-tap trilerp
            int base = ((x0l * TY + y0l) << 6) + z0l;
            float v000 = __half2float(tile[base]);
            float v001 = __half2float(tile[base + 1]);
            float v010 = __half2float(tile[base + TZ]);
            float v011 = __half2float(tile[base + TZ + 1]);
            float v100 = __half2float(tile[base + TY * TZ]);
            float v101 = __half2float(tile[base + TY * TZ + 1]);
            float v110 = __half2float(tile[base + TY * TZ + TZ]);
            float v111 = __half2float(tile[base + TY * TZ + TZ + 1]);
            float c00 = fmaf(1.0f - tz, v000, tz * v001);
            float c01 = fmaf(1.0f - tz, v010, tz * v011);
            float c10 = fmaf(1.0f - tz, v100, tz * v101);
            float c11 = fmaf(1.0f - tz, v110, tz * v111);
            float d0 = fmaf(1.0f - ty, c00, ty * c01);
            float d1 = fmaf(1.0f - ty, c10, ty * c11);
            res = fmaf(1.0f - tx, d0, tx * d1);
        } else {
            res = sample_masked(img, tx, ty, tz, x0, y0, z0);
        }
        outb[r] = res;
    }
}

} // namespace

extern "C" void kernel_launch(void* const* d_in, const int* in_sizes, int n_in,
                              void* d_out, int out_size) {
    const float* image = (const float*)d_in[0];  // (B, 1, H, W, D) fp32
    const float* ddf   = (const float*)d_in[1];  // (B, 3, H, W, D) fp32
    float* out         = (float*)d_out;          // (B, 1, H, W, D) fp32

    static bool attr_set = false;
    if (!attr_set) {
        cudaFuncSetAttribute(warp_kernel, cudaFuncAttributeMaxDynamicSharedMemorySize,
                             SMEM_BYTES);
        attr_set = true;
    }

    int pack_threads = (B * N) / 8;              // 524,288
    pack16_kernel<<<pack_threads / 256, 256>>>(image);

    int bricks = B * (H / BX) * (W / BY) * (D / BZ);   // 512
    warp_kernel<<<bricks, 1024, SMEM_BYTES>>>(ddf, out);
}

// round 7
// speedup vs baseline: 2.0523x; 1.3551x over previous
#include <cuda_runtime.h>
#include <cuda_fp16.h>
#include <cstdint>

namespace {

constexpr int H = 128, W = 128, D = 128;
constexpr int N = H * W * D;          // 2^21
constexpr int B = 2;

// brick / tile geometry
constexpr int BX = 16, BY = 8, BZ = 32;         // voxels per block (4096)
constexpr int HALO = 8;                         // 8-aligned z chunks
constexpr int TX = BX + 2 * HALO + 1;           // 33
constexpr int TY = BY + 2 * HALO + 1;           // 25
constexpr int TZ = 56;                          // 49 needed, pad to mult of 8
constexpr int NROWS = TX * TY;                  // 825
constexpr int SMEM_BYTES = NROWS * TZ * 2;      // 92,400

// fp16 copy of the image (staging reads + rare fallback gathers)
__device__ __align__(16) __half g_img16[(size_t)B * N];

// ---------------- prepass: fp32 image -> fp16 copy ----------------
__global__ __launch_bounds__(256) void pack16_kernel(const float* __restrict__ img) {
    int t = blockIdx.x * blockDim.x + threadIdx.x;
    int base = t * 8;
    float4 a = *reinterpret_cast<const float4*>(img + base);
    float4 c = *reinterpret_cast<const float4*>(img + base + 4);
    __half2 h[4];
    h[0] = __floats2half2_rn(a.x, a.y);
    h[1] = __floats2half2_rn(a.z, a.w);
    h[2] = __floats2half2_rn(c.x, c.y);
    h[3] = __floats2half2_rn(c.z, c.w);
    *reinterpret_cast<uint4*>(g_img16 + base) = *reinterpret_cast<uint4*>(h);
}

// rare fallback: fully masked trilinear gather from global fp16 image
__device__ __noinline__ float sample_masked(const __half* __restrict__ img,
                                            float tx, float ty, float tz,
                                            int x0, int y0, int z0) {
    int x1 = x0 + 1, y1 = y0 + 1, z1 = z0 + 1;
    float wx0 = ((unsigned)x0 < (unsigned)H) ? (1.0f - tx) : 0.0f;
    float wx1 = ((unsigned)x1 < (unsigned)H) ? tx          : 0.0f;
    float wy0 = ((unsigned)y0 < (unsigned)W) ? (1.0f - ty) : 0.0f;
    float wy1 = ((unsigned)y1 < (unsigned)W) ? ty          : 0.0f;
    float wz0 = ((unsigned)z0 < (unsigned)D) ? (1.0f - tz) : 0.0f;
    float wz1 = ((unsigned)z1 < (unsigned)D) ? tz          : 0.0f;
    int cx0 = min(max(x0, 0), H - 1), cx1 = min(max(x1, 0), H - 1);
    int cy0 = min(max(y0, 0), W - 1), cy1 = min(max(y1, 0), W - 1);
    int cz0 = min(max(z0, 0), D - 1), cz1 = min(max(z1, 0), D - 1);
    int bx0 = cx0 * (W * D), bx1 = cx1 * (W * D);
    int by0 = cy0 * D,       by1 = cy1 * D;
    float v000 = __half2float(__ldg(img + bx0 + by0 + cz0));
    float v001 = __half2float(__ldg(img + bx0 + by0 + cz1));
    float v010 = __half2float(__ldg(img + bx0 + by1 + cz0));
    float v011 = __half2float(__ldg(img + bx0 + by1 + cz1));
    float v100 = __half2float(__ldg(img + bx1 + by0 + cz0));
    float v101 = __half2float(__ldg(img + bx1 + by0 + cz1));
    float v110 = __half2float(__ldg(img + bx1 + by1 + cz0));
    float v111 = __half2float(__ldg(img + bx1 + by1 + cz1));
    float c00 = fmaf(wz0, v000, wz1 * v001);
    float c01 = fmaf(wz0, v010, wz1 * v011);
    float c10 = fmaf(wz0, v100, wz1 * v101);
    float c11 = fmaf(wz0, v110, wz1 * v111);
    float d0 = fmaf(wy0, c00, wy1 * c01);
    float d1 = fmaf(wy0, c10, wy1 * c11);
    return fmaf(wx0, d0, wx1 * d1);
}

__device__ __forceinline__ void cp16(unsigned int smem_addr, const void* gptr, int src_bytes) {
    asm volatile("cp.async.cg.shared.global [%0], [%1], 16, %2;\n"
                 :: "r"(smem_addr), "l"(gptr), "r"(src_bytes));
}

// ---------------- main kernel: one 16x8x32 brick per 512-thread block ----------------
__global__ __launch_bounds__(512, 2) void warp_kernel(const float* __restrict__ ddf,
                                                      float* __restrict__ out) {
    extern __shared__ __half tile[];   // [TX=33][TY=25][TZ=56]

    int bid = blockIdx.x;
    int bz = bid & 3;
    int by = (bid >> 2) & 15;
    int bx = (bid >> 6) & 7;
    int b  = bid >> 9;

    int X0 = bx * BX, Y0 = by * BY, Z0 = bz * BZ;
    int gx0 = X0 - HALO, gy0 = Y0 - HALO, gz0 = Z0 - HALO;   // gz0 multiple of 8

    const __half* img = g_img16 + (size_t)b * N;
    int tid = threadIdx.x;
    int warp = tid >> 5, lane = tid & 31;

    // ---- stage via cp.async: 4 rows per warp-iter, 7 x 16B chunks per row ----
    // lane -> (sub-row = lane/7, chunk = lane%7); lanes 28..31 idle.
    {
        int lrow = lane / 7;            // 0..4
        int lchk = lane - lrow * 7;     // 0..6
        bool lactive = lane < 28;
        int zoff = lchk * 8;            // half offset within row (16B chunks)
        int gzc = gz0 + zoff;           // chunk global z start (8-aligned)
        bool zok = (unsigned)gzc < (unsigned)D;   // whole chunk in [0,128)
        unsigned int tbase = (unsigned int)__cvta_generic_to_shared(tile);

        #pragma unroll 1
        for (int rb = warp * 4; rb < NROWS; rb += 16 * 4) {
            int row = rb + lrow;
            if (lactive && row < NROWS) {
                unsigned i = (unsigned)row / (unsigned)TY;
                unsigned j = (unsigned)row - i * TY;
                int gx = gx0 + (int)i, gy = gy0 + (int)j;
                bool ok = ((unsigned)gx < (unsigned)H) & ((unsigned)gy < (unsigned)W) & zok;
                int cgx = min(max(gx, 0), H - 1), cgy = min(max(gy, 0), W - 1);
                const void* src = img + (((cgx << 7) | cgy) << 7) + (ok ? gzc : 0);
                unsigned int dst = tbase + (unsigned int)(row * TZ + zoff) * 2u;
                cp16(dst, src, ok ? 16 : 0);   // src_bytes=0 -> zero-fill (padding)
            }
        }
        asm volatile("cp.async.commit_group;\n");
        asm volatile("cp.async.wait_group 0;\n");
    }
    __syncthreads();

    // ---- compute: 8 iters, one (x,y) column of 32 z-voxels per warp ----
    const float* dbase0 = ddf + (size_t)b * 3 * N;
    float* outb = out + (size_t)b * N;

    #pragma unroll
    for (int it = 0; it < 8; it++) {
        int row = it * 16 + warp;        // 0..127
        int xl = row >> 3, yl = row & 7;
        int x = X0 + xl, y = Y0 + yl, z = Z0 + lane;
        int r = ((x << 7 | y) << 7) | z;

        float fx = (float)x + __ldg(dbase0 + r);
        float fy = (float)y + __ldg(dbase0 + N + r);
        float fz = (float)z + __ldg(dbase0 + 2 * N + r);

        float x0f = floorf(fx), y0f = floorf(fy), z0f = floorf(fz);
        float tx = fx - x0f, ty = fy - y0f, tz = fz - z0f;
        int x0 = (int)x0f, y0 = (int)y0f, z0 = (int)z0f;

        int x0l = x0 - gx0, y0l = y0 - gy0, z0l = z0 - gz0;
        bool bad = ((unsigned)x0l > (unsigned)(TX - 2)) |
                   ((unsigned)y0l > (unsigned)(TY - 2)) |
                   ((unsigned)z0l > (unsigned)(TZ - 2));

        float res;
        if (!bad) {
            // zeros-padding baked into the staged tile: unmasked 8-tap trilerp
            int base = (x0l * TY + y0l) * TZ + z0l;
            float v000 = __half2float(tile[base]);
            float v001 = __half2float(tile[base + 1]);
            float v010 = __half2float(tile[base + TZ]);
            float v011 = __half2float(tile[base + TZ + 1]);
            float v100 = __half2float(tile[base + TY * TZ]);
            float v101 = __half2float(tile[base + TY * TZ + 1]);
            float v110 = __half2float(tile[base + TY * TZ + TZ]);
            float v111 = __half2float(tile[base + TY * TZ + TZ + 1]);
            float c00 = fmaf(1.0f - tz, v000, tz * v001);
            float c01 = fmaf(1.0f - tz, v010, tz * v011);
            float c10 = fmaf(1.0f - tz, v100, tz * v101);
            float c11 = fmaf(1.0f - tz, v110, tz * v111);
            float d0 = fmaf(1.0f - ty, c00, ty * c01);
            float d1 = fmaf(1.0f - ty, c10, ty * c11);
            res = fmaf(1.0f - tx, d0, tx * d1);
        } else {
            res = sample_masked(img, tx, ty, tz, x0, y0, z0);
        }
        outb[r] = res;
    }
}

} // namespace

extern "C" void kernel_launch(void* const* d_in, const int* in_sizes, int n_in,
                              void* d_out, int out_size) {
    const float* image = (const float*)d_in[0];  // (B, 1, H, W, D) fp32
    const float* ddf   = (const float*)d_in[1];  // (B, 3, H, W, D) fp32
    float* out         = (float*)d_out;          // (B, 1, H, W, D) fp32

    static bool attr_set = false;
    if (!attr_set) {
        cudaFuncSetAttribute(warp_kernel, cudaFuncAttributeMaxDynamicSharedMemorySize,
                             SMEM_BYTES);
        attr_set = true;
    }

    int pack_threads = (B * N) / 8;              // 524,288
    pack16_kernel<<<pack_threads / 256, 256>>>(image);

    int bricks = B * (H / BX) * (W / BY) * (D / BZ);   // 1024
    warp_kernel<<<bricks, 512, SMEM_BYTES>>>(ddf, out);
}

// round 8
// speedup vs baseline: 2.0795x; 1.0132x over previous
#include <cuda_runtime.h>
#include <cuda_fp16.h>
#include <cstdint>

namespace {

constexpr int H = 128, W = 128, D = 128;
constexpr int N = H * W * D;          // 2^21
constexpr int B = 2;

// brick / tile geometry
constexpr int BX = 16, BY = 8, BZ = 32;         // voxels per block (4096)
constexpr int HALO = 8;                         // 8-aligned z chunks
constexpr int TX = BX + 2 * HALO + 1;           // 33
constexpr int TY = BY + 2 * HALO + 1;           // 25
constexpr int TZE = BZ + 2 * HALO + 1;          // 49 usable z entries
constexpr int TZ = 64;                          // padded: shift addressing
constexpr int NROWS = TX * TY;                  // 825
constexpr int SMEM_BYTES = NROWS * TZ * 2;      // 105,600 (x2 CTAs = 211KB < 228KB)

// fp16 copy of the image (staging reads + rare fallback gathers)
__device__ __align__(16) __half g_img16[(size_t)B * N];

// ---------------- prepass: fp32 image -> fp16 copy ----------------
__global__ __launch_bounds__(256) void pack16_kernel(const float* __restrict__ img) {
    int t = blockIdx.x * blockDim.x + threadIdx.x;
    int base = t * 8;
    float4 a = *reinterpret_cast<const float4*>(img + base);
    float4 c = *reinterpret_cast<const float4*>(img + base + 4);
    __half2 h[4];
    h[0] = __floats2half2_rn(a.x, a.y);
    h[1] = __floats2half2_rn(a.z, a.w);
    h[2] = __floats2half2_rn(c.x, c.y);
    h[3] = __floats2half2_rn(c.z, c.w);
    *reinterpret_cast<uint4*>(g_img16 + base) = *reinterpret_cast<uint4*>(h);
}

// rare fallback: fully masked trilinear gather from global fp16 image
__device__ __noinline__ float sample_masked(const __half* __restrict__ img,
                                            float tx, float ty, float tz,
                                            int x0, int y0, int z0) {
    int x1 = x0 + 1, y1 = y0 + 1, z1 = z0 + 1;
    float wx0 = ((unsigned)x0 < (unsigned)H) ? (1.0f - tx) : 0.0f;
    float wx1 = ((unsigned)x1 < (unsigned)H) ? tx          : 0.0f;
    float wy0 = ((unsigned)y0 < (unsigned)W) ? (1.0f - ty) : 0.0f;
    float wy1 = ((unsigned)y1 < (unsigned)W) ? ty          : 0.0f;
    float wz0 = ((unsigned)z0 < (unsigned)D) ? (1.0f - tz) : 0.0f;
    float wz1 = ((unsigned)z1 < (unsigned)D) ? tz          : 0.0f;
    int cx0 = min(max(x0, 0), H - 1), cx1 = min(max(x1, 0), H - 1);
    int cy0 = min(max(y0, 0), W - 1), cy1 = min(max(y1, 0), W - 1);
    int cz0 = min(max(z0, 0), D - 1), cz1 = min(max(z1, 0), D - 1);
    int bx0 = cx0 * (W * D), bx1 = cx1 * (W * D);
    int by0 = cy0 * D,       by1 = cy1 * D;
    float v000 = __half2float(__ldg(img + bx0 + by0 + cz0));
    float v001 = __half2float(__ldg(img + bx0 + by0 + cz1));
    float v010 = __half2float(__ldg(img + bx0 + by1 + cz0));
    float v011 = __half2float(__ldg(img + bx0 + by1 + cz1));
    float v100 = __half2float(__ldg(img + bx1 + by0 + cz0));
    float v101 = __half2float(__ldg(img + bx1 + by0 + cz1));
    float v110 = __half2float(__ldg(img + bx1 + by1 + cz0));
    float v111 = __half2float(__ldg(img + bx1 + by1 + cz1));
    float c00 = fmaf(wz0, v000, wz1 * v001);
    float c01 = fmaf(wz0, v010, wz1 * v011);
    float c10 = fmaf(wz0, v100, wz1 * v101);
    float c11 = fmaf(wz0, v110, wz1 * v111);
    float d0 = fmaf(wy0, c00, wy1 * c01);
    float d1 = fmaf(wy0, c10, wy1 * c11);
    return fmaf(wx0, d0, wx1 * d1);
}

__device__ __forceinline__ void cp16(unsigned int smem_addr, const void* gptr, int src_bytes) {
    asm volatile("cp.async.cg.shared.global [%0], [%1], 16, %2;\n"
                 :: "r"(smem_addr), "l"(gptr), "r"(src_bytes));
}

// ---------------- main kernel: one 16x8x32 brick per 512-thread block ----------------
__global__ __launch_bounds__(512, 2) void warp_kernel(const float* __restrict__ ddf,
                                                      float* __restrict__ out) {
    extern __shared__ __half tile[];   // [TX=33][TY=25][TZ=64]

    int bid = blockIdx.x;
    int bz = bid & 3;
    int by = (bid >> 2) & 15;
    int bx = (bid >> 6) & 7;
    int b  = bid >> 9;

    int X0 = bx * BX, Y0 = by * BY, Z0 = bz * BZ;
    int gx0 = X0 - HALO, gy0 = Y0 - HALO, gz0 = Z0 - HALO;   // gz0 multiple of 8

    const __half* img = g_img16 + (size_t)b * N;
    int tid = threadIdx.x;
    int warp = tid >> 5, lane = tid & 31;

    // ---- stage via cp.async: 4 rows per warp-iter, 7 x 16B chunks per row ----
    {
        int lrow = lane / 7;            // 0..4
        int lchk = lane - lrow * 7;     // 0..6
        bool lactive = lane < 28;
        int zoff = lchk * 8;            // half offset within row (16B chunks)
        int gzc = gz0 + zoff;           // chunk global z start (8-aligned)
        bool zok = (unsigned)gzc < (unsigned)D;
        unsigned int tbase = (unsigned int)__cvta_generic_to_shared(tile);

        #pragma unroll 1
        for (int rb = warp * 4; rb < NROWS; rb += 16 * 4) {
            int row = rb + lrow;
            if (lactive && row < NROWS) {
                unsigned i = (unsigned)row / (unsigned)TY;
                unsigned j = (unsigned)row - i * TY;
                int gx = gx0 + (int)i, gy = gy0 + (int)j;
                bool ok = ((unsigned)gx < (unsigned)H) & ((unsigned)gy < (unsigned)W) & zok;
                int cgx = min(max(gx, 0), H - 1), cgy = min(max(gy, 0), W - 1);
                const void* src = img + (((cgx << 7) | cgy) << 7) + (ok ? gzc : 0);
                unsigned int dst = tbase + (unsigned int)((row << 6) + zoff) * 2u;
                cp16(dst, src, ok ? 16 : 0);   // src_bytes=0 -> zero-fill (padding)
            }
        }
        asm volatile("cp.async.commit_group;\n");
        asm volatile("cp.async.wait_group 0;\n");
    }
    __syncthreads();

    // ---- compute: 8 iters; x steps by +2 per iter -> constant pointer strides ----
    const float* dbase0 = ddf + (size_t)b * 3 * N;
    float* outb = out + (size_t)b * N;

    int xl = warp >> 3, yl = warp & 7;                 // starting local coords
    int xs = X0 + xl, y = Y0 + yl, z = Z0 + lane;
    int r0 = ((xs << 7 | y) << 7) | z;
    constexpr int RSTEP = 2 << 14;                     // x += 2 per iteration

    const float* pd = dbase0 + r0;
    float dx = __ldg(pd), dy = __ldg(pd + N), dz = __ldg(pd + 2 * N);

    int rcur = r0;
    int x = xs;

    #pragma unroll
    for (int it = 0; it < 8; it++) {
        float cdx = dx, cdy = dy, cdz = dz;
        if (it < 7) {                                   // prefetch next iteration
            pd += RSTEP;
            dx = __ldg(pd); dy = __ldg(pd + N); dz = __ldg(pd + 2 * N);
        }

        float fx = (float)x + cdx;
        float fy = (float)y + cdy;
        float fz = (float)z + cdz;

        float x0f = floorf(fx), y0f = floorf(fy), z0f = floorf(fz);
        float tx = fx - x0f, ty = fy - y0f, tz = fz - z0f;
        int x0 = (int)x0f, y0 = (int)y0f, z0 = (int)z0f;

        int x0l = x0 - gx0, y0l = y0 - gy0, z0l = z0 - gz0;
        bool bad = ((unsigned)x0l > (unsigned)(TX - 2)) |
                   ((unsigned)y0l > (unsigned)(TY - 2)) |
                   ((unsigned)z0l > (unsigned)(TZE - 2));

        float res;
        if (!bad) {
            // zeros-padding baked into the staged tile: unmasked 8-tap trilerp
            int base = ((x0l * TY + y0l) << 6) + z0l;
            float v000 = __half2float(tile[base]);
            float v001 = __half2float(tile[base + 1]);
            float v010 = __half2float(tile[base + TZ]);
            float v011 = __half2float(tile[base + TZ + 1]);
            float v100 = __half2float(tile[base + TY * TZ]);
            float v101 = __half2float(tile[base + TY * TZ + 1]);
            float v110 = __half2float(tile[base + TY * TZ + TZ]);
            float v111 = __half2float(tile[base + TY * TZ + TZ + 1]);
            float c00 = fmaf(1.0f - tz, v000, tz * v001);
            float c01 = fmaf(1.0f - tz, v010, tz * v011);
            float c10 = fmaf(1.0f - tz, v100, tz * v101);
            float c11 = fmaf(1.0f - tz, v110, tz * v111);
            float d0 = fmaf(1.0f - ty, c00, ty * c01);
            float d1 = fmaf(1.0f - ty, c10, ty * c11);
            res = fmaf(1.0f - tx, d0, tx * d1);
        } else {
            res = sample_masked(img, tx, ty, tz, x0, y0, z0);
        }
        outb[rcur] = res;
        rcur += RSTEP;
        x += 2;
    }
}

} // namespace

extern "C" void kernel_launch(void* const* d_in, const int* in_sizes, int n_in,
                              void* d_out, int out_size) {
    const float* image = (const float*)d_in[0];  // (B, 1, H, W, D) fp32
    const float* ddf   = (const float*)d_in[1];  // (B, 3, H, W, D) fp32
    float* out         = (float*)d_out;          // (B, 1, H, W, D) fp32

    static bool attr_set = false;
    if (!attr_set) {
        cudaFuncSetAttribute(warp_kernel, cudaFuncAttributeMaxDynamicSharedMemorySize,
                             SMEM_BYTES);
        attr_set = true;
    }

    int pack_threads = (B * N) / 8;              // 524,288
    pack16_kernel<<<pack_threads / 256, 256>>>(image);

    int bricks = B * (H / BX) * (W / BY) * (D / BZ);   // 1024
    warp_kernel<<<bricks, 512, SMEM_BYTES>>>(ddf, out);
}